// round 6
// baseline (speedup 1.0000x reference)
#include <cuda_runtime.h>
#include <cstdint>

// AccumulateLoss: CONTINLEN=5 pose-consistency loss.
// inputs: d_in[0] = rotas  (10, B, 3, 3) fp32
//         d_in[1] = transs (10, B, 3)    fp32
// output: d_out[0] = sum((R1@R2 - R12)^2)*50 + sum((R1@t1 + t2 - t12)^2)

#define NPAIRS 10
#define BETA   50.0f
#define BLOCK_B 64
#define NBLOCKS 444                  // 148 SMs x 3 resident CTAs (smem-limited)
#define RSLAB   (BLOCK_B * 9)        // 576 floats per pair R slab
#define TSLAB   (BLOCK_B * 3)        // 192 floats per pair t slab
#define RBUF_F  (NPAIRS * RSLAB)     // 5760 floats
#define TBUF_F  (NPAIRS * TSLAB)     // 1920 floats
#define STAGE_F (RBUF_F + TBUF_F)    // 7680 floats = 30720 B per stage
#define SMEM_BYTES (2 * STAGE_F * 4) // 61440 B (double-buffered)

// triples (i,k,j) flattened to pair ids: (p1, p2, p12) — literal constants.
#define FOR_EACH_TRIPLE(X) \
    X(0,4,1) X(0,5,2) X(0,6,3) X(1,7,2) X(1,8,3) \
    X(2,9,3) X(4,7,5) X(4,8,6) X(5,9,6) X(7,9,8)

__device__ double g_acc;              // zero-init; reset by last block each launch
__device__ unsigned int g_counter;    // zero-init; reset by last block each launch

__device__ __forceinline__ uint32_t smem_u32(const void* p) {
    return (uint32_t)__cvta_generic_to_shared(p);
}
__device__ __forceinline__ void cp_async16(uint32_t s, const void* g) {
    asm volatile("cp.async.cg.shared.global [%0], [%1], 16;\n" :: "r"(s), "l"(g));
}
__device__ __forceinline__ void cp_async4(uint32_t s, const void* g) {
    asm volatile("cp.async.ca.shared.global [%0], [%1], 4;\n" :: "r"(s), "l"(g));
}
__device__ __forceinline__ void cp_commit() {
    asm volatile("cp.async.commit_group;\n" ::: "memory");
}
__device__ __forceinline__ void cp_wait1() {
    asm volatile("cp.async.wait_group 1;\n" ::: "memory");
}

extern __shared__ float sm[];   // 2 stages: [R(5760) | t(1920)] x 2

__global__ __launch_bounds__(BLOCK_B)
void accum_loss_kernel(const float* __restrict__ rotas,
                       const float* __restrict__ transs,
                       float* __restrict__ out,
                       int B, int ntiles, int nblocks) {
    const int tid  = threadIdx.x;
    const int lane = tid & 31;
    const int wid  = tid >> 5;

    const size_t PB9 = (size_t)B * 9;
    const size_t PB3 = (size_t)B * 3;

    // ---- prefetch one full tile (R + t) into stage `buf` via cp.async ----
    auto prefetch = [&](int tile, int buf) {
        const int b0 = tile * BLOCK_B;
        const int nvalid = min(BLOCK_B, B - b0);
        float* stR = sm + buf * STAGE_F;
        float* stT = stR + RBUF_F;
        if (nvalid == BLOCK_B) {
            #pragma unroll
            for (int p = 0; p < NPAIRS; p++) {
                const float4* g = (const float4*)(rotas + (size_t)p * PB9 + (size_t)b0 * 9);
                uint32_t s = smem_u32(stR + p * RSLAB);
                #pragma unroll
                for (int i = tid; i < RSLAB / 4; i += BLOCK_B)     // 144 float4/pair
                    cp_async16(s + i * 16, g + i);
            }
            #pragma unroll
            for (int p = 0; p < NPAIRS; p++) {
                const float4* g = (const float4*)(transs + (size_t)p * PB3 + (size_t)b0 * 3);
                uint32_t s = smem_u32(stT + p * TSLAB);
                if (tid < TSLAB / 4)                               // 48 float4/pair
                    cp_async16(s + tid * 16, g + tid);
            }
        } else {
            for (int p = 0; p < NPAIRS; p++) {
                const float* g = rotas + (size_t)p * PB9 + (size_t)b0 * 9;
                uint32_t s = smem_u32(stR + p * RSLAB);
                for (int i = tid; i < nvalid * 9; i += BLOCK_B)
                    cp_async4(s + i * 4, g + i);
            }
            for (int p = 0; p < NPAIRS; p++) {
                const float* g = transs + (size_t)p * PB3 + (size_t)b0 * 3;
                uint32_t s = smem_u32(stT + p * TSLAB);
                for (int i = tid; i < nvalid * 3; i += BLOCK_B)
                    cp_async4(s + i * 4, g + i);
            }
        }
    };

    float loss = 0.0f;

    int tile = blockIdx.x;
    int buf = 0;
    if (tile < ntiles) prefetch(tile, 0);
    cp_commit();

    for (; tile < ntiles; tile += nblocks) {
        const int b0 = tile * BLOCK_B;
        const int nvalid = min(BLOCK_B, B - b0);

        // Issue next tile's async loads BEFORE waiting on the current tile —
        // the DRAM queue stays fed through compute + wait.
        const int nxt = tile + nblocks;
        if (nxt < ntiles) prefetch(nxt, buf ^ 1);
        cp_commit();           // exactly one group per iteration

        cp_wait1();            // everything but the newest group done
        __syncthreads();

        if (tid < nvalid) {
            const float* stR = sm + buf * STAGE_F;
            const float* stT = stR + RBUF_F;

            // 90 conflict-free LDS (stride 9, gcd(9,32)=1)
            float r[NPAIRS][9];
            const float* myR = stR + tid * 9;
            #pragma unroll
            for (int p = 0; p < NPAIRS; p++) {
                #pragma unroll
                for (int e = 0; e < 9; e++)
                    r[p][e] = myR[p * RSLAB + e];
            }
            // 30 conflict-free LDS (stride 3, gcd(3,32)=1)
            float t[NPAIRS][3];
            const float* myT = stT + tid * 3;
            #pragma unroll
            for (int p = 0; p < NPAIRS; p++) {
                t[p][0] = myT[p * TSLAB + 0];
                t[p][1] = myT[p * TSLAB + 1];
                t[p][2] = myT[p * TSLAB + 2];
            }

            float ra = 0.0f, ta = 0.0f;

            #define DO_TRIPLE(p1, p2, p12)                                     \
            {                                                                  \
                _Pragma("unroll")                                              \
                for (int i = 0; i < 3; i++) {                                  \
                    _Pragma("unroll")                                          \
                    for (int j = 0; j < 3; j++) {                              \
                        float s = fmaf(r[p1][i*3+0], r[p2][0*3+j],             \
                                  fmaf(r[p1][i*3+1], r[p2][1*3+j],             \
                                       r[p1][i*3+2] * r[p2][2*3+j]));          \
                        float d = s - r[p12][i*3+j];                           \
                        ra = fmaf(d, d, ra);                                   \
                    }                                                          \
                }                                                              \
                _Pragma("unroll")                                              \
                for (int i = 0; i < 3; i++) {                                  \
                    float s = fmaf(r[p1][i*3+0], t[p1][0],                     \
                              fmaf(r[p1][i*3+1], t[p1][1],                     \
                              fmaf(r[p1][i*3+2], t[p1][2], t[p2][i])));        \
                    float d = s - t[p12][i];                                   \
                    ta = fmaf(d, d, ta);                                       \
                }                                                              \
            }

            FOR_EACH_TRIPLE(DO_TRIPLE)
            #undef DO_TRIPLE

            loss += fmaf(ra, BETA, ta);
        }

        __syncthreads();        // all reads of sm[buf] done before refill next iter
        buf ^= 1;
    }

    // ---- Block reduction ----
    #pragma unroll
    for (int off = 16; off > 0; off >>= 1)
        loss += __shfl_down_sync(0xffffffffu, loss, off);

    __shared__ double warp_sums[BLOCK_B / 32];
    __shared__ bool is_last;
    if (lane == 0) warp_sums[wid] = (double)loss;
    __syncthreads();

    if (tid == 0) {
        double s = 0.0;
        #pragma unroll
        for (int w = 0; w < BLOCK_B / 32; w++) s += warp_sums[w];
        atomicAdd(&g_acc, s);
        __threadfence();
        unsigned int done = atomicAdd(&g_counter, 1u);
        is_last = (done == (unsigned)nblocks - 1u);
    }
    __syncthreads();

    // ---- Last block writes result and resets state for the next graph replay ----
    if (is_last && tid == 0) {
        unsigned long long old = atomicExch((unsigned long long*)&g_acc, 0ull);
        out[0] = (float)__longlong_as_double((long long)old);
        __threadfence();
        g_counter = 0u;
    }
}

extern "C" void kernel_launch(void* const* d_in, const int* in_sizes, int n_in,
                              void* d_out, int out_size) {
    const float* rotas  = (const float*)d_in[0];
    const float* transs = (const float*)d_in[1];
    float* out = (float*)d_out;

    const int B = in_sizes[0] / (NPAIRS * 9);
    const int ntiles = (B + BLOCK_B - 1) / BLOCK_B;   // 4096 for B=262144
    const int nblocks = (ntiles < NBLOCKS) ? ntiles : NBLOCKS;

    // >48KB dynamic smem opt-in (non-stream call; safe under graph capture)
    cudaFuncSetAttribute(accum_loss_kernel,
                         cudaFuncAttributeMaxDynamicSharedMemorySize, SMEM_BYTES);

    accum_loss_kernel<<<nblocks, BLOCK_B, SMEM_BYTES>>>(rotas, transs, out,
                                                        B, ntiles, nblocks);
}

// round 7
// speedup vs baseline: 1.0119x; 1.0119x over previous
#include <cuda_runtime.h>
#include <cstdint>

// AccumulateLoss: CONTINLEN=5 pose-consistency loss.
// inputs: d_in[0] = rotas  (10, B, 3, 3) fp32
//         d_in[1] = transs (10, B, 3)    fp32
// output: d_out[0] = sum((R1@R2 - R12)^2)*50 + sum((R1@t1 + t2 - t12)^2)
//
// Warp-autonomous double-buffered pipelines: each warp owns a 32-element tile
// and a private smem slab; no __syncthreads in the main loop -> warps free-run
// and self-stagger, smoothing DRAM demand.

#define NPAIRS 10
#define BETA   50.0f
#define WTILE  32                    // batch elements per warp-tile
#define WARPS_PER_CTA 2
#define BLOCK_T (WARPS_PER_CTA * 32) // 64 threads
#define NBLOCKS 592                  // 148 SMs x 4 CTAs (smem: 46KB/CTA)
#define WSLAB_F (WTILE * 9)          // 288 floats per pair per warp-tile
#define WSTAGE_F (NPAIRS * WSLAB_F)  // 2880 floats = 11520 B per stage

// triples (i,k,j) flattened to pair ids: (p1, p2, p12) — literal constants.
#define FOR_EACH_TRIPLE(X) \
    X(0,4,1) X(0,5,2) X(0,6,3) X(1,7,2) X(1,8,3) \
    X(2,9,3) X(4,7,5) X(4,8,6) X(5,9,6) X(7,9,8)

__device__ double g_acc;              // zero-init; reset by last block each launch
__device__ unsigned int g_counter;    // zero-init; reset by last block each launch

__device__ __forceinline__ uint32_t smem_u32(const void* p) {
    return (uint32_t)__cvta_generic_to_shared(p);
}
__device__ __forceinline__ void cp_async16(uint32_t s, const void* g) {
    asm volatile("cp.async.cg.shared.global [%0], [%1], 16;\n" :: "r"(s), "l"(g));
}
__device__ __forceinline__ void cp_async4(uint32_t s, const void* g) {
    asm volatile("cp.async.ca.shared.global [%0], [%1], 4;\n" :: "r"(s), "l"(g));
}
__device__ __forceinline__ void cp_commit() {
    asm volatile("cp.async.commit_group;\n" ::: "memory");
}
__device__ __forceinline__ void cp_wait1() {
    asm volatile("cp.async.wait_group 1;\n" ::: "memory");
}

__global__ __launch_bounds__(BLOCK_T)
void accum_loss_kernel(const float* __restrict__ rotas,
                       const float* __restrict__ transs,
                       float* __restrict__ out,
                       int B, int nwt, int totalwarps) {
    // per-warp private double-buffered R slabs: [warp][buf][2880 floats]
    __shared__ float sR[WARPS_PER_CTA][2][WSTAGE_F];   // 46080 B

    const int lane = threadIdx.x & 31;
    const int wid  = threadIdx.x >> 5;
    const int gwarp = blockIdx.x * WARPS_PER_CTA + wid;

    const size_t PB9 = (size_t)B * 9;
    const size_t PB3 = (size_t)B * 3;

    // ---- prefetch this warp-tile's R into stage `buf` (warp-collective) ----
    auto prefetch = [&](int wt, int buf) {
        const int b0 = wt * WTILE;
        const int nvalid = min(WTILE, B - b0);
        float* st = sR[wid][buf];
        if (nvalid == WTILE) {
            #pragma unroll
            for (int p = 0; p < NPAIRS; p++) {
                const float4* g = (const float4*)(rotas + (size_t)p * PB9 + (size_t)b0 * 9);
                uint32_t s = smem_u32(st + p * WSLAB_F);
                #pragma unroll
                for (int i = 0; i < 3; i++) {            // 72 float4 per pair
                    int idx = i * 32 + lane;
                    if (idx < WSLAB_F / 4)
                        cp_async16(s + idx * 16, g + idx);
                }
            }
        } else {
            for (int p = 0; p < NPAIRS; p++) {
                const float* g = rotas + (size_t)p * PB9 + (size_t)b0 * 9;
                uint32_t s = smem_u32(st + p * WSLAB_F);
                for (int i = lane; i < nvalid * 9; i += 32)
                    cp_async4(s + i * 4, g + i);
            }
        }
    };

    float loss = 0.0f;

    int wt = gwarp;
    int buf = 0;
    if (wt < nwt) prefetch(wt, 0);
    cp_commit();

    for (; wt < nwt; wt += totalwarps) {
        const int b0 = wt * WTILE;
        const int nvalid = min(WTILE, B - b0);

        // t: direct per-thread LDG (warp covers 384 dense bytes/pair) —
        // issued before the wait so its latency overlaps the pipeline wait.
        float t[NPAIRS][3];
        if (lane < nvalid) {
            const int b = b0 + lane;
            #pragma unroll
            for (int p = 0; p < NPAIRS; p++) {
                const float* src = transs + (size_t)p * PB3 + (size_t)b * 3;
                t[p][0] = src[0]; t[p][1] = src[1]; t[p][2] = src[2];
            }
        }

        // issue next tile's loads before waiting on the current tile
        const int nxt = wt + totalwarps;
        if (nxt < nwt) prefetch(nxt, buf ^ 1);
        cp_commit();            // exactly one group per iteration

        cp_wait1();             // all but the newest group complete
        __syncwarp();           // all lanes' groups done before any lane reads

        if (lane < nvalid) {
            const float* st = sR[wid][buf];
            // 90 conflict-free LDS (stride 9, gcd(9,32)=1)
            float r[NPAIRS][9];
            const float* myR = st + lane * 9;
            #pragma unroll
            for (int p = 0; p < NPAIRS; p++) {
                #pragma unroll
                for (int e = 0; e < 9; e++)
                    r[p][e] = myR[p * WSLAB_F + e];
            }

            float ra = 0.0f, ta = 0.0f;

            #define DO_TRIPLE(p1, p2, p12)                                     \
            {                                                                  \
                _Pragma("unroll")                                              \
                for (int i = 0; i < 3; i++) {                                  \
                    _Pragma("unroll")                                          \
                    for (int j = 0; j < 3; j++) {                              \
                        float s = fmaf(r[p1][i*3+0], r[p2][0*3+j],             \
                                  fmaf(r[p1][i*3+1], r[p2][1*3+j],             \
                                       r[p1][i*3+2] * r[p2][2*3+j]));          \
                        float d = s - r[p12][i*3+j];                           \
                        ra = fmaf(d, d, ra);                                   \
                    }                                                          \
                }                                                              \
                _Pragma("unroll")                                              \
                for (int i = 0; i < 3; i++) {                                  \
                    float s = fmaf(r[p1][i*3+0], t[p1][0],                     \
                              fmaf(r[p1][i*3+1], t[p1][1],                     \
                              fmaf(r[p1][i*3+2], t[p1][2], t[p2][i])));        \
                    float d = s - t[p12][i];                                   \
                    ta = fmaf(d, d, ta);                                       \
                }                                                              \
            }

            FOR_EACH_TRIPLE(DO_TRIPLE)
            #undef DO_TRIPLE

            loss += fmaf(ra, BETA, ta);
        }

        __syncwarp();           // lanes done reading sR[wid][buf] before refill
        buf ^= 1;
    }

    // ---- Reduction: warp -> CTA -> global ----
    #pragma unroll
    for (int off = 16; off > 0; off >>= 1)
        loss += __shfl_down_sync(0xffffffffu, loss, off);

    __shared__ double warp_sums[WARPS_PER_CTA];
    __shared__ bool is_last;
    if (lane == 0) warp_sums[wid] = (double)loss;
    __syncthreads();

    if (threadIdx.x == 0) {
        double s = 0.0;
        #pragma unroll
        for (int w = 0; w < WARPS_PER_CTA; w++) s += warp_sums[w];
        atomicAdd(&g_acc, s);
        __threadfence();
        unsigned int done = atomicAdd(&g_counter, 1u);
        is_last = (done == gridDim.x - 1u);
    }
    __syncthreads();

    // ---- Last block writes result and resets state for the next graph replay ----
    if (is_last && threadIdx.x == 0) {
        unsigned long long old = atomicExch((unsigned long long*)&g_acc, 0ull);
        out[0] = (float)__longlong_as_double((long long)old);
        __threadfence();
        g_counter = 0u;
    }
}

extern "C" void kernel_launch(void* const* d_in, const int* in_sizes, int n_in,
                              void* d_out, int out_size) {
    const float* rotas  = (const float*)d_in[0];
    const float* transs = (const float*)d_in[1];
    float* out = (float*)d_out;

    const int B = in_sizes[0] / (NPAIRS * 9);
    const int nwt = (B + WTILE - 1) / WTILE;          // warp-tiles (8192)
    int nblocks = NBLOCKS;
    if (nblocks * WARPS_PER_CTA > nwt)
        nblocks = (nwt + WARPS_PER_CTA - 1) / WARPS_PER_CTA;
    const int totalwarps = nblocks * WARPS_PER_CTA;

    accum_loss_kernel<<<nblocks, BLOCK_T>>>(rotas, transs, out, B, nwt, totalwarps);
}